// round 10
// baseline (speedup 1.0000x reference)
#include <cuda_runtime.h>
#include <cstdint>

#define BB 64
#define TT 1024
#define DD 64
#define HH 256
#define NGRP 4        // batch groups per layer (16 batches each)
#define NBAT 16       // batches per group
#define NT 512        // 16 warps

typedef unsigned long long ull;

// ---------------- device-global scratch ----------------
__device__ float    d_h1s[(size_t)TT * NGRP * HH * 16];   // l0 hidden stream k-major [T][grp][H][16b]
__device__ float    d_hbA[4 * NGRP * HH * 16];            // l0 h rotation [4][grp][H][16b]
__device__ float    d_hbB[4 * NGRP * HH * 16];            // l1 h rotation
__device__ float    d_h2s[BB * HH];                       // l1 final h [B][H]
__device__ unsigned d_flag[2 * NGRP * 16];                // monotonic per-slice progress

__device__ __forceinline__ ull splat2(float w) {
    ull d; asm("mov.b64 %0, {%1, %1};" : "=l"(d) : "f"(w)); return d;
}
__device__ __forceinline__ void fma2(ull& d, ull a, ull b) {
    asm("fma.rn.f32x2 %0, %1, %2, %0;" : "+l"(d) : "l"(a), "l"(b));
}
__device__ __forceinline__ ull add2(ull a, ull b) {
    ull d; asm("add.rn.f32x2 %0, %1, %2;" : "=l"(d) : "l"(a), "l"(b)); return d;
}
__device__ __forceinline__ float sigf(float x)   { return 1.f / (1.f + __expf(-x)); }
__device__ __forceinline__ float tanhfs(float x) { return 1.f - 2.f / (1.f + __expf(2.f * x)); }
__device__ __forceinline__ void st_release(unsigned* p, unsigned v) {
    asm volatile("st.global.release.gpu.u32 [%0], %1;" :: "l"(p), "r"(v) : "memory");
}
__device__ __forceinline__ unsigned ld_acquire(const unsigned* p) {
    unsigned v; asm volatile("ld.global.acquire.gpu.u32 %0, [%1];" : "=r"(v) : "l"(p)); return v;
}
// wait (lanes 0,1) until flags[s0] and flags[s0+1] reach tgt, then warp-converge
__device__ __forceinline__ void wait2(const unsigned* flags, int s0, unsigned tgt, int lane) {
    if (lane < 2) {
        const unsigned* f = flags + s0 + lane;
        while (ld_acquire(f) < tgt) {}
    }
    __syncwarp(0xFFFFFFFFu);
}

// 8 chunks x 4 k: weights from registers, inputs broadcast from smem.
// Accumulates rows (lane) and (lane+32) over 16 batches (8 f32x2 pairs each).
__device__ __forceinline__ void gemm32(const float* __restrict__ wA,
                                       const float* __restrict__ wB,
                                       const float* __restrict__ vk0,
                                       ull* aA, ull* aB)
{
#pragma unroll
    for (int c = 0; c < 8; ++c) {
        const float* vk = vk0 + 4 * c * 16;
#pragma unroll
        for (int j = 0; j < 4; ++j) {
            const ulonglong2* vp = reinterpret_cast<const ulonglong2*>(vk + j * 16);
            ulonglong2 q0 = vp[0], q1 = vp[1], q2 = vp[2], q3 = vp[3];
            ull wsa = splat2(wA[4 * c + j]);
            ull wsb = splat2(wB[4 * c + j]);
            fma2(aA[0], wsa, q0.x); fma2(aA[1], wsa, q0.y);
            fma2(aA[2], wsa, q1.x); fma2(aA[3], wsa, q1.y);
            fma2(aA[4], wsa, q2.x); fma2(aA[5], wsa, q2.y);
            fma2(aA[6], wsa, q3.x); fma2(aA[7], wsa, q3.y);
            fma2(aB[0], wsb, q0.x); fma2(aB[1], wsb, q0.y);
            fma2(aB[2], wsb, q1.x); fma2(aB[3], wsb, q1.y);
            fma2(aB[4], wsb, q2.x); fma2(aB[5], wsb, q2.y);
            fma2(aB[6], wsb, q3.x); fma2(aB[7], wsb, q3.y);
        }
    }
}

// One LSTM layer, persistent. CTA = 16 units x 16 batches (64 gate rows), 16 warps.
// Warps [0, XW): x-warps (k range w*32 of the input); warps [8,16): h-warps
// (k range (w-8)*32 of h). Weights live in registers (2 rows x 32 k per thread).
template <int KIN, int LAYER, int XW>
__device__ __forceinline__ void layer_body(
    const float* __restrict__ in0,           // l0: x [B][T][D]; l1: d_h1s k-major [T][grp][H][16]
    const float* __restrict__ Wih, const float* __restrict__ Whh,
    const float* __restrict__ bih, const float* __restrict__ bhh,
    float* hb, float* hstream, int grp, int slice)
{
    constexpr int KTOT = KIN + HH;
    constexpr int PKU  = 64 * 9;        // sP per-warp stride in ull (row pad: 8+1 ull)

    extern __shared__ float sm[];
    float* sV = sm;                     // [KTOT][16]  (x | h), k-major
    float* sP = sV + KTOT * 16;         // [16][64][18] partial pairs (ull view)
    float* sG = sP + 16 * PKU * 2;      // [64][16] reduced gates
    float* sB = sG + 64 * 16;           // [64] bias
    float* sC = sB + 64;                // [256] cell (u*16+b)
    ull*   sPu = reinterpret_cast<ull*>(sP);
    ull*   sGu = reinterpret_cast<ull*>(sG);

    const int tid   = threadIdx.x;
    const int w     = tid >> 5;
    const int lane  = tid & 31;
    const int bbase = grp * NBAT;
    const int ubase = slice * 16;
    unsigned* ownflags = &d_flag[(LAYER * NGRP + grp) * 16];
    unsigned* srcflags = &d_flag[grp * 16];               // layer-0 flags (l1 x-dep)
    unsigned* myflag   = ownflags + slice;
    const unsigned fbase = *(volatile unsigned*)myflag;   // lockstep across all flags

    const bool isx = (w < XW);
    const bool ish = (w >= 8);
    const int  hw  = w - 8;

    // ---- one-time: weights -> registers (2 rows x 32 k per thread) ----
    const int RA = ((lane >> 4) << 8) + ubase + (lane & 15);          // rows lane: gates 0,1
    const int RB = (((lane + 32) >> 4) << 8) + ubase + (lane & 15);   // rows lane+32: gates 2,3
    float wRA[32], wRB[32];
    if (isx) {
        const float4* a = reinterpret_cast<const float4*>(Wih + (long long)RA * KIN + w * 32);
        const float4* b = reinterpret_cast<const float4*>(Wih + (long long)RB * KIN + w * 32);
#pragma unroll
        for (int i = 0; i < 8; ++i) {
            *reinterpret_cast<float4*>(wRA + 4 * i) = a[i];
            *reinterpret_cast<float4*>(wRB + 4 * i) = b[i];
        }
    } else if (ish) {
        const float4* a = reinterpret_cast<const float4*>(Whh + (long long)RA * HH + hw * 32);
        const float4* b = reinterpret_cast<const float4*>(Whh + (long long)RB * HH + hw * 32);
#pragma unroll
        for (int i = 0; i < 8; ++i) {
            *reinterpret_cast<float4*>(wRA + 4 * i) = a[i];
            *reinterpret_cast<float4*>(wRB + 4 * i) = b[i];
        }
    }

    // zero partial buffer (idle warps never write theirs), bias, cell, h[0]
    for (int i = tid; i < 16 * PKU * 2; i += NT) sP[i] = 0.f;
    if (tid < 64) {
        int R = ((tid >> 4) << 8) + ubase + (tid & 15);
        sB[tid] = bih[R] + bhh[R];
    }
    if (tid < 256) sC[tid] = 0.f;
    if (tid < 64) {
        float4 z = make_float4(0.f, 0.f, 0.f, 0.f);
        int u = tid >> 2, q = tid & 3;
        *reinterpret_cast<float4*>(hb + ((size_t)(0 * NGRP + grp) * HH + ubase + u) * 16 + q * 4) = z;
    }
    __syncthreads();
    if (tid == 0) st_release(myflag, fbase + 1);

    const int koff = isx ? (w * 32) : (KIN + hw * 32);   // k offset in sV
    const float* vbase = sV + koff * 16;
    // l0 x staging: lane -> batch lane>>1, k half (lane&1)
    const float* xsrc0 = (LAYER == 0)
        ? in0 + (size_t)(bbase + (lane >> 1)) * TT * DD + w * 32 + (lane & 1) * 16 : nullptr;

    ull aA[8], aB[8];

    for (int t = 0; t < TT; ++t) {
        // ---- [A] per-warp: stage + gemm ----
        if (isx) {
            if (LAYER == 0) {
                const float4* s4 = reinterpret_cast<const float4*>(xsrc0 + (size_t)t * DD);
#pragma unroll
                for (int i = 0; i < 4; ++i) {
                    float4 v = s4[i];
                    int k0 = w * 32 + (lane & 1) * 16 + 4 * i;
                    float* d = sV + k0 * 16 + (lane >> 1);
                    d[0] = v.x; d[16] = v.y; d[32] = v.z; d[48] = v.w;
                }
            } else {
                wait2(srcflags, 2 * w, fbase + (unsigned)t + 2u, lane);
                const float4* src = reinterpret_cast<const float4*>(in0) +
                                    ((size_t)(t * NGRP + grp) * KIN + w * 32) * 4;
                float4* dst = reinterpret_cast<float4*>(sV) + (w * 32) * 4;
#pragma unroll
                for (int i = 0; i < 4; ++i) dst[lane + 32 * i] = __ldcv(src + lane + 32 * i);
            }
        } else if (ish) {
            wait2(ownflags, 2 * hw, fbase + (unsigned)t + 1u, lane);
            const float4* src = reinterpret_cast<const float4*>(hb) +
                                ((size_t)((t & 3) * NGRP + grp) * HH + hw * 32) * 4;
            float4* dst = reinterpret_cast<float4*>(sV) + ((KIN + hw * 32)) * 4;
#pragma unroll
            for (int i = 0; i < 4; ++i) dst[lane + 32 * i] = __ldcv(src + lane + 32 * i);
        }
        if (isx || ish) {
            __syncwarp(0xFFFFFFFFu);
#pragma unroll
            for (int i = 0; i < 8; ++i) { aA[i] = 0; aB[i] = 0; }
            gemm32(wRA, wRB, vbase, aA, aB);
            ull* pA = sPu + w * PKU + lane * 9;
            ull* pB = sPu + w * PKU + (lane + 32) * 9;
#pragma unroll
            for (int i = 0; i < 8; ++i) { pA[i] = aA[i]; pB[i] = aB[i]; }
        }
        __syncthreads();

        // ---- [B] reduce 16 partials: thread = (row r, batch pair bp) ----
        {
            int r = tid >> 3, bp = tid & 7;
            ull acc = splat2(sB[r]);
            const ull* p = sPu + r * 9 + bp;
#pragma unroll
            for (int q = 0; q < 16; ++q) acc = add2(acc, p[q * PKU]);
            sGu[r * 8 + bp] = acc;
        }
        __syncthreads();

        // ---- [C] pointwise + publish: thread = (unit u, batch b) ----
        if (tid < 256) {
            int u = tid >> 4, b = tid & 15;
            float iv = sigf(sG[(u)       * 16 + b]);
            float fv = sigf(sG[(16 + u)  * 16 + b]);
            float gg = tanhfs(sG[(32 + u) * 16 + b]);
            float ov = sigf(sG[(48 + u)  * 16 + b]);
            float c  = fv * sC[tid] + iv * gg;
            sC[tid] = c;
            float hv = ov * tanhfs(c);
            hb[((size_t)((((t + 1) & 3) * NGRP) + grp) * HH + ubase + u) * 16 + b] = hv;
            if (LAYER == 0)
                hstream[((size_t)(t * NGRP + grp) * HH + ubase + u) * 16 + b] = hv;
            if (LAYER == 1 && t == TT - 1)
                d_h2s[(size_t)(bbase + b) * HH + ubase + u] = hv;
        }
        __syncthreads();            // publish issued; sP/sG consumed
        if (tid == 0) st_release(myflag, fbase + (unsigned)t + 2u);
    }
}

__global__ void __launch_bounds__(NT, 1) rnn_fused(
    const float* __restrict__ x,
    const float* __restrict__ Wih0, const float* __restrict__ Whh0,
    const float* __restrict__ bih0, const float* __restrict__ bhh0,
    const float* __restrict__ Wih1, const float* __restrict__ Whh1,
    const float* __restrict__ bih1, const float* __restrict__ bhh1)
{
    int bid   = blockIdx.x;
    int layer = bid >> 6;
    int sub   = bid & 63;
    int grp   = sub >> 4;
    int slice = sub & 15;

    if (layer == 0) {
        layer_body<DD, 0, 2>(x, Wih0, Whh0, bih0, bhh0, d_hbA, d_h1s, grp, slice);
    } else {
        layer_body<HH, 1, 8>(d_h1s, Wih1, Whh1, bih1, bhh1, d_hbB, nullptr, grp, slice);
    }
}

// out[b] = dot(h2_last[b][:], fc_w) + fc_b
__global__ void fc_kernel(const float* __restrict__ fcw,
                          const float* __restrict__ fcb,
                          float* __restrict__ out)
{
    int b = blockIdx.x, tid = threadIdx.x;
    const float* h = d_h2s + (size_t)b * HH;
    float s = 0.f;
    for (int k = tid; k < HH; k += 128) s += h[k] * fcw[k];
    for (int o = 16; o > 0; o >>= 1) s += __shfl_xor_sync(0xFFFFFFFFu, s, o);
    __shared__ float ws[4];
    if ((tid & 31) == 0) ws[tid >> 5] = s;
    __syncthreads();
    if (tid == 0) out[b] = ws[0] + ws[1] + ws[2] + ws[3] + fcb[0];
}

extern "C" void kernel_launch(void* const* d_in, const int* in_sizes, int n_in,
                              void* d_out, int out_size)
{
    const float* x     = (const float*)d_in[0];
    const float* W_ih0 = (const float*)d_in[1];
    const float* W_hh0 = (const float*)d_in[2];
    const float* b_ih0 = (const float*)d_in[3];
    const float* b_hh0 = (const float*)d_in[4];
    const float* W_ih1 = (const float*)d_in[5];
    const float* W_hh1 = (const float*)d_in[6];
    const float* b_ih1 = (const float*)d_in[7];
    const float* b_hh1 = (const float*)d_in[8];
    const float* fc_w  = (const float*)d_in[9];
    const float* fc_b  = (const float*)d_in[10];
    float* out = (float*)d_out;

    // smem (l1 layout, the larger): sV + sP + sG + sB + sC
    const int SMB = ((HH + HH) * 16 + 16 * 64 * 18 + 64 * 16 + 64 + 256) * 4; // 111,872

    cudaFuncSetAttribute(rnn_fused, cudaFuncAttributeMaxDynamicSharedMemorySize, SMB);

    rnn_fused<<<128, NT, SMB>>>(x, W_ih0, W_hh0, b_ih0, b_hh0,
                                W_ih1, W_hh1, b_ih1, b_hh1);
    fc_kernel<<<BB, 128>>>(fc_w, fc_b, out);
}